// round 16
// baseline (speedup 1.0000x reference)
#include <cuda_runtime.h>
#include <cuda_fp16.h>
#include <cstdint>
#include <math.h>

// ---------------- problem constants ----------------
#define TOK   65536          // 2*32*32*32 tokens
#define CDIM  512
#define QKVN  1536
#define HIDN  2048
#define NWIN  1024           // windows total (2 * 8^3)
#define NHEAD 8
#define HD    64

// ---------------- helpers ----------------
__device__ __forceinline__ uint32_t smem_to_u32(const void* p) {
    uint32_t a;
    asm("{ .reg .u64 t; cvta.to.shared.u64 t, %1; cvt.u32.u64 %0, t; }" : "=r"(a) : "l"(p));
    return a;
}

#define CP_ASYNC16(dst, src) \
    asm volatile("cp.async.cg.shared.global [%0], [%1], 16;" :: "r"(dst), "l"(src))
#define CP_COMMIT() asm volatile("cp.async.commit_group;" ::: "memory")
#define CP_WAIT0()  asm volatile("cp.async.wait_group 0;" ::: "memory")
#define CP_WAIT2()  asm volatile("cp.async.wait_group 2;" ::: "memory")

#define LDSM_X4(r0, r1, r2, r3, addr) \
    asm volatile("ldmatrix.sync.aligned.m8n8.x4.shared.b16 {%0,%1,%2,%3}, [%4];" \
                 : "=r"(r0), "=r"(r1), "=r"(r2), "=r"(r3) : "r"(addr))

#define LDSM_X4_T(r0, r1, r2, r3, addr) \
    asm volatile("ldmatrix.sync.aligned.m8n8.x4.trans.shared.b16 {%0,%1,%2,%3}, [%4];" \
                 : "=r"(r0), "=r"(r1), "=r"(r2), "=r"(r3) : "r"(addr))

__device__ __forceinline__ void mma_f16(float* c, const uint32_t* a, const uint32_t* b) {
    asm volatile(
        "mma.sync.aligned.m16n8k16.row.col.f32.f16.f16.f32 "
        "{%0,%1,%2,%3}, {%4,%5,%6,%7}, {%8,%9}, {%0,%1,%2,%3};"
        : "+f"(c[0]), "+f"(c[1]), "+f"(c[2]), "+f"(c[3])
        : "r"(a[0]), "r"(a[1]), "r"(a[2]), "r"(a[3]), "r"(b[0]), "r"(b[1]));
}

// ---------------- scratch (static device memory) ----------------
__device__ float  g_xo  [(size_t)TOK * CDIM];                 // fp32 residual base
__device__ __half g_qkv [(size_t)TOK * QKVN];                 // fp16 qkv
__device__ __half g_y1 [(size_t)TOK * CDIM];
__device__ __half g_at [(size_t)TOK * CDIM];
__device__ __half g_y2 [(size_t)TOK * CDIM];
__device__ __half g_hid[(size_t)TOK * HIDN];
// weight transposed fp16 buffers: [N, K]
__device__ __half g_wqkv[(size_t)QKVN * CDIM];
__device__ __half g_wprj[(size_t)CDIM * CDIM];
__device__ __half g_w1  [(size_t)HIDN * CDIM];
__device__ __half g_w2  [(size_t)CDIM * HIDN];

// window-ordered row r -> natural token index t
__device__ __forceinline__ int wr2t(int r) {
    int n   = r & 63;
    int win = r >> 6;
    int ww  = win & 7, wh = (win >> 3) & 7, wd = (win >> 6) & 7, b = win >> 9;
    int zw  = n & 3,  zh = (n >> 2) & 3,  zd = n >> 4;
    int d = (wd * 4 + zd + 2) & 31;
    int h = (wh * 4 + zh + 2) & 31;
    int w = (ww * 4 + zw + 2) & 31;
    return ((b * 32 + d) * 32 + h) * 32 + w;
}

__device__ __forceinline__ float gelu_exact(float v) {
    return 0.5f * v * (1.0f + erff(v * 0.70710678118654752f));
}

// ---------------- weight transpose -> fp16 (all four weights, one launch) --
__global__ __launch_bounds__(256)
void wconv_all(const float* __restrict__ W0, const float* __restrict__ W1,
               const float* __restrict__ W2, const float* __restrict__ W3,
               __half* __restrict__ T0, __half* __restrict__ T1,
               __half* __restrict__ T2, __half* __restrict__ T3)
{
    __shared__ float tile[32][33];
    int t = blockIdx.x;
    const float* W; __half* Wt; int K, N, u, nx;
    if (t < 768)       { W = W0; Wt = T0; K = 512;  N = 1536; u = t;        nx = 48; }
    else if (t < 1024) { W = W1; Wt = T1; K = 512;  N = 512;  u = t - 768;  nx = 16; }
    else if (t < 2048) { W = W2; Wt = T2; K = 512;  N = 2048; u = t - 1024; nx = 64; }
    else               { W = W3; Wt = T3; K = 2048; N = 512;  u = t - 2048; nx = 16; }
    int n0 = (u % nx) * 32, k0 = (u / nx) * 32;
    int tx = threadIdx.x & 31, ty = threadIdx.x >> 5;   // 32 x 8
    #pragma unroll
    for (int r = 0; r < 4; r++) {
        int kk = ty + r * 8;
        tile[kk][tx] = W[(size_t)(k0 + kk) * N + n0 + tx];
    }
    __syncthreads();
    #pragma unroll
    for (int r = 0; r < 4; r++) {
        int nn = ty + r * 8;
        Wt[(size_t)(n0 + nn) * K + k0 + tx] = __float2half_rn(tile[tx][nn]);
    }
}

// ---------------- LayerNorm -> fp16 ----------------
__global__ __launch_bounds__(256)
void ln_kernel(const float* __restrict__ X, const float* __restrict__ gam,
               const float* __restrict__ bet, __half* __restrict__ Y, int gather)
{
    __shared__ float red[16];
    int r   = blockIdx.x;
    int src = gather ? wr2t(r) : r;
    const float* xr = X + (size_t)src * CDIM;
    int t = threadIdx.x;
    float v0 = xr[t], v1 = xr[t + 256];
    float s = v0 + v1;
    float q = v0 * v0 + v1 * v1;
    #pragma unroll
    for (int off = 16; off > 0; off >>= 1) {
        s += __shfl_xor_sync(0xffffffffu, s, off);
        q += __shfl_xor_sync(0xffffffffu, q, off);
    }
    int w = t >> 5, lane = t & 31;
    if (lane == 0) { red[w] = s; red[8 + w] = q; }
    __syncthreads();
    if (w == 0) {
        float s2 = (lane < 8) ? red[lane] : 0.f;
        float q2 = (lane < 8) ? red[8 + lane] : 0.f;
        #pragma unroll
        for (int off = 4; off > 0; off >>= 1) {
            s2 += __shfl_xor_sync(0xffffffffu, s2, off);
            q2 += __shfl_xor_sync(0xffffffffu, q2, off);
        }
        if (lane == 0) { red[0] = s2; red[1] = q2; }
    }
    __syncthreads();
    float mean = red[0] * (1.0f / CDIM);
    float var  = red[1] * (1.0f / CDIM) - mean * mean;
    float rstd = rsqrtf(var + 1e-5f);
    size_t rb = (size_t)r * CDIM;
    float y0 = (v0 - mean) * rstd * gam[t]       + bet[t];
    float y1 = (v1 - mean) * rstd * gam[t + 256] + bet[t + 256];
    Y[rb + t]       = __float2half_rn(y0);
    Y[rb + t + 256] = __float2half_rn(y1);
}

// ---------------- tensor-core GEMM via mma.sync (pure fp16, fp32 acc) ------
// CTA 128x128, 4 warps in 2(M)x2(N), warp tile 64x64, BK=32.
// A operand bypasses shared memory: fragments loaded straight from gmem
// (LDG.32) with one-chunk register double-buffering. Only B is staged in
// smem (4-stage cp.async ring) -> crossbar traffic halved vs R14.
#define EPI_NONE    0
#define EPI_GELU    1
#define EPI_RES_MAP 2
#define EPI_RES_NAT 3

#define ROWPITCH 80
#define BUFSZ    10240         // B only: 128 rows * 80B
#define NSTAGE   4
#define GT_SMEM  (NSTAGE * BUFSZ)   // 40960 B

template<int EPI, int OUTH>
__global__ __launch_bounds__(128, 2)
void gemm_mma(const __half* __restrict__ A, const __half* __restrict__ B,
              const float* __restrict__ bias, const float* __restrict__ R,
              float* __restrict__ C, __half* __restrict__ Ch, int M, int N, int K)
{
    extern __shared__ char sm[];
    const uint32_t smb = smem_to_u32(sm);
    const int tid  = threadIdx.x;
    const int wid  = tid >> 5, lane = tid & 31;
    const int wm   = wid & 1,  wn   = wid >> 1;          // 2(M) x 2(N)
    const int row0 = blockIdx.y * 128, col0 = blockIdx.x * 128;

    const int g = lane >> 3, r = lane & 7;
    const uint32_t boff = (uint32_t)((wn * 64 + (g >> 1) * 8 + r) * ROWPITCH + (g & 1) * 16);

    const int qr = lane >> 2, qc2 = (lane & 3) * 2;
    const __half* Ab = A + (size_t)(row0 + wm * 64 + qr) * K + qc2;

    float acc[4][8][4];
    #pragma unroll
    for (int i = 0; i < 4; i++)
        #pragma unroll
        for (int j = 0; j < 8; j++)
            #pragma unroll
            for (int e = 0; e < 4; e++) acc[i][j][e] = 0.f;

    const int NC = K >> 5;

    // B loader: 128 rows x 4 segs = 512 segs / 128 thr = 4 each
    auto load_chunkB = [&](int kc, int buf) {
        const uint32_t bb = smb + buf * BUFSZ;
        #pragma unroll
        for (int i = 0; i < 4; i++) {
            int u   = tid + (i << 7);          // 0..511
            int row = u >> 2, seg = u & 3;
            CP_ASYNC16(bb + (uint32_t)(row * ROWPITCH + seg * 16),
                       B + (size_t)(col0 + row) * K + kc + seg * 8);
        }
        CP_COMMIT();
    };

    // A fragment loader: 32 LDG.32 per thread per chunk
    auto load_afrags = [&](int kc, uint32_t (*dst)[2][4]) {
        #pragma unroll
        for (int mi = 0; mi < 4; mi++) {
            const __half* pm = Ab + (size_t)(mi * 16) * K + kc;
            #pragma unroll
            for (int s = 0; s < 2; s++) {
                const __half* p = pm + s * 16;
                dst[mi][s][0] = *(const uint32_t*)(p);
                dst[mi][s][1] = *(const uint32_t*)(p + 8 * (size_t)K);
                dst[mi][s][2] = *(const uint32_t*)(p + 8);
                dst[mi][s][3] = *(const uint32_t*)(p + 8 * (size_t)K + 8);
            }
        }
    };

    auto compute = [&](int c, uint32_t (*afr)[2][4]) {
        const uint32_t ab = smb + (c & 3) * BUFSZ;
        #pragma unroll
        for (int s = 0; s < 2; s++) {
            uint32_t bh[8][2];
            #pragma unroll
            for (int nj = 0; nj < 4; nj++) {
                uint32_t addr = ab + boff + nj * (16 * ROWPITCH) + s * 32;
                LDSM_X4(bh[nj*2][0], bh[nj*2][1], bh[nj*2+1][0], bh[nj*2+1][1], addr);
            }
            #pragma unroll
            for (int mi = 0; mi < 4; mi++)
                #pragma unroll
                for (int ni = 0; ni < 8; ni++)
                    mma_f16(acc[mi][ni], afr[mi][s], bh[ni]);
        }
    };

    uint32_t aA[4][2][4], aB[4][2][4];

    // prologue: B stages 0..2 in flight; A chunk 0 in regs
    load_chunkB(0, 0);
    load_chunkB(32, 1);
    load_chunkB(64, 2);
    load_afrags(0, aA);

    for (int c = 0; c < NC; c += 2) {
        // even chunk c (cur = aA)
        load_afrags((c + 1) * 32, aB);            // prefetch next A
        CP_WAIT2();
        __syncthreads();
        if (c + 3 < NC) load_chunkB((c + 3) * 32, (c + 3) & 3);
        compute(c, aA);

        // odd chunk c+1 (cur = aB)
        if (c + 2 < NC) load_afrags((c + 2) * 32, aA);
        CP_WAIT2();
        __syncthreads();
        if (c + 4 < NC) load_chunkB((c + 4) * 32, (c + 4) & 3);
        compute(c + 1, aB);
    }

    // ---- epilogue ----
    const int qrow = lane >> 2;
    const int qcol = (lane & 3) * 2;
    #pragma unroll
    for (int mi = 0; mi < 4; mi++) {
        int gr0 = row0 + wm * 64 + mi * 16 + qrow;
        int gr1 = gr0 + 8;
        int or0 = (EPI == EPI_RES_MAP) ? wr2t(gr0) : gr0;
        int or1 = (EPI == EPI_RES_MAP) ? wr2t(gr1) : gr1;
        #pragma unroll
        for (int ni = 0; ni < 8; ni++) {
            int col = col0 + wn * 64 + ni * 8 + qcol;
            float b0 = bias[col], b1 = bias[col + 1];
            float v00 = acc[mi][ni][0] + b0, v01 = acc[mi][ni][1] + b1;
            float v10 = acc[mi][ni][2] + b0, v11 = acc[mi][ni][3] + b1;
            if (EPI == EPI_GELU) {
                v00 = gelu_exact(v00); v01 = gelu_exact(v01);
                v10 = gelu_exact(v10); v11 = gelu_exact(v11);
            }
            if (EPI == EPI_RES_MAP || EPI == EPI_RES_NAT) {
                float2 r0v = *(const float2*)(R + (size_t)or0 * N + col);
                float2 r1v = *(const float2*)(R + (size_t)or1 * N + col);
                v00 += r0v.x; v01 += r0v.y; v10 += r1v.x; v11 += r1v.y;
            }
            if (OUTH) {
                *(__half2*)(Ch + (size_t)or0 * N + col) =
                    __halves2half2(__float2half_rn(v00), __float2half_rn(v01));
                *(__half2*)(Ch + (size_t)or1 * N + col) =
                    __halves2half2(__float2half_rn(v10), __float2half_rn(v11));
            } else {
                *(float2*)(C + (size_t)or0 * N + col) = make_float2(v00, v01);
                *(float2*)(C + (size_t)or1 * N + col) = make_float2(v10, v11);
            }
        }
    }
}

// ---------------- tensor-core windowed attention, register-resident P ------
#define AP 72        // half pitch (144 B)
#define ATTN_SMEM (3 * 64 * AP * 2)   // q,k,v only: 27648 B

__global__ __launch_bounds__(128)
void attn_kernel(const __half* __restrict__ qkv, __half* __restrict__ out)
{
    extern __shared__ char smc[];
    __half* qs = (__half*)smc;                  // 64 x 72
    __half* ks = qs + 64 * AP;
    __half* vs = ks + 64 * AP;
    const uint32_t qb = smem_to_u32(qs), kb = smem_to_u32(ks), vb = smem_to_u32(vs);

    const int tid = threadIdx.x, w = tid >> 5, lane = tid & 31;
    const int win = blockIdx.x >> 3, head = blockIdx.x & 7;
    const __half* src = qkv + (size_t)win * 64 * QKVN + head * HD;

    #pragma unroll
    for (int j = 0; j < 12; j++) {
        int u = tid + (j << 7);
        int tile = u >> 9, rem = u & 511;
        int row = rem >> 3, seg = rem & 7;
        uint32_t db = (tile == 0 ? qb : (tile == 1 ? kb : vb)) + row * 144 + seg * 16;
        CP_ASYNC16(db, src + tile * 512 + (size_t)row * QKVN + seg * 8);
    }
    CP_COMMIT();
    CP_WAIT0();
    __syncthreads();

    const int g = lane >> 3, r = lane & 7;
    const uint32_t a_q = qb + (w * 16 + (g & 1) * 8 + r) * 144 + (g >> 1) * 16;

    // ---- S = Q K^T ----
    float sacc[8][4];
    #pragma unroll
    for (int i = 0; i < 8; i++)
        #pragma unroll
        for (int e = 0; e < 4; e++) sacc[i][e] = 0.f;
    #pragma unroll
    for (int s = 0; s < 4; s++) {
        uint32_t af[4];
        LDSM_X4(af[0], af[1], af[2], af[3], a_q + s * 32);
        #pragma unroll
        for (int ng = 0; ng < 4; ng++) {
            uint32_t bf[4];
            LDSM_X4(bf[0], bf[1], bf[2], bf[3],
                    kb + ((g >> 1) * 8 + r + ng * 16) * 144 + (g & 1) * 16 + s * 32);
            mma_f16(sacc[ng * 2],     af, &bf[0]);
            mma_f16(sacc[ng * 2 + 1], af, &bf[2]);
        }
    }

    // ---- softmax (quad reduce) ----
    float mx0 = -1e30f, mx1 = -1e30f;
    #pragma unroll
    for (int i = 0; i < 8; i++) {
        sacc[i][0] *= 0.125f; sacc[i][1] *= 0.125f;
        sacc[i][2] *= 0.125f; sacc[i][3] *= 0.125f;
        mx0 = fmaxf(mx0, fmaxf(sacc[i][0], sacc[i][1]));
        mx1 = fmaxf(mx1, fmaxf(sacc[i][2], sacc[i][3]));
    }
    mx0 = fmaxf(mx0, __shfl_xor_sync(0xffffffffu, mx0, 1));
    mx0 = fmaxf(mx0, __shfl_xor_sync(0xffffffffu, mx0, 2));
    mx1 = fmaxf(mx1, __shfl_xor_sync(0xffffffffu, mx1, 1));
    mx1 = fmaxf(mx1, __shfl_xor_sync(0xffffffffu, mx1, 2));
    float sm0 = 0.f, sm1 = 0.f;
    #pragma unroll
    for (int i = 0; i < 8; i++) {
        sacc[i][0] = __expf(sacc[i][0] - mx0);
        sacc[i][1] = __expf(sacc[i][1] - mx0);
        sacc[i][2] = __expf(sacc[i][2] - mx1);
        sacc[i][3] = __expf(sacc[i][3] - mx1);
        sm0 += sacc[i][0] + sacc[i][1];
        sm1 += sacc[i][2] + sacc[i][3];
    }
    sm0 += __shfl_xor_sync(0xffffffffu, sm0, 1);
    sm0 += __shfl_xor_sync(0xffffffffu, sm0, 2);
    sm1 += __shfl_xor_sync(0xffffffffu, sm1, 1);
    sm1 += __shfl_xor_sync(0xffffffffu, sm1, 2);
    const float inv0 = 1.0f / sm0, inv1 = 1.0f / sm1;

    // ---- pack P into A-fragments ----
    uint32_t pa[4][4];
    #pragma unroll
    for (int t = 0; t < 4; t++) {
        __half2 h;
        h = __halves2half2(__float2half_rn(sacc[2*t][0] * inv0),
                           __float2half_rn(sacc[2*t][1] * inv0));
        pa[t][0] = *(uint32_t*)&h;
        h = __halves2half2(__float2half_rn(sacc[2*t][2] * inv1),
                           __float2half_rn(sacc[2*t][3] * inv1));
        pa[t][1] = *(uint32_t*)&h;
        h = __halves2half2(__float2half_rn(sacc[2*t+1][0] * inv0),
                           __float2half_rn(sacc[2*t+1][1] * inv0));
        pa[t][2] = *(uint32_t*)&h;
        h = __halves2half2(__float2half_rn(sacc[2*t+1][2] * inv1),
                           __float2half_rn(sacc[2*t+1][3] * inv1));
        pa[t][3] = *(uint32_t*)&h;
    }

    // ---- O = P V ----
    float oacc[8][4];
    #pragma unroll
    for (int i = 0; i < 8; i++)
        #pragma unroll
        for (int e = 0; e < 4; e++) oacc[i][e] = 0.f;
    #pragma unroll
    for (int kk = 0; kk < 2; kk++) {
        #pragma unroll
        for (int nd = 0; nd < 8; nd++) {
            uint32_t vf[4];
            LDSM_X4_T(vf[0], vf[1], vf[2], vf[3],
                      vb + (kk * 32 + g * 8 + r) * 144 + nd * 16);
            mma_f16(oacc[nd], pa[2*kk],     &vf[0]);
            mma_f16(oacc[nd], pa[2*kk + 1], &vf[2]);
        }
    }

    // ---- store O ----
    const int qr = lane >> 2, qc = (lane & 3) * 2;
    __half* dst = out + ((size_t)win * 64) * CDIM + head * HD;
    const int m0 = w * 16 + qr;
    #pragma unroll
    for (int nd = 0; nd < 8; nd++) {
        int d = nd * 8 + qc;
        *(__half2*)(dst + (size_t)m0 * CDIM + d) =
            __halves2half2(__float2half_rn(oacc[nd][0]), __float2half_rn(oacc[nd][1]));
        *(__half2*)(dst + (size_t)(m0 + 8) * CDIM + d) =
            __halves2half2(__float2half_rn(oacc[nd][2]), __float2half_rn(oacc[nd][3]));
    }
}

// ---------------- launch ----------------
extern "C" void kernel_launch(void* const* d_in, const int* in_sizes, int n_in,
                              void* d_out, int out_size)
{
    const float* x      = (const float*)d_in[0];
    const float* ln1_g  = (const float*)d_in[1];
    const float* ln1_b  = (const float*)d_in[2];
    const float* qkv_w  = (const float*)d_in[3];
    const float* qkv_b  = (const float*)d_in[4];
    const float* proj_w = (const float*)d_in[5];
    const float* proj_b = (const float*)d_in[6];
    const float* ln2_g  = (const float*)d_in[7];
    const float* ln2_b  = (const float*)d_in[8];
    const float* ffn_w1 = (const float*)d_in[9];
    const float* ffn_b1 = (const float*)d_in[10];
    const float* ffn_w2 = (const float*)d_in[11];
    const float* ffn_b2 = (const float*)d_in[12];
    float* out = (float*)d_out;

    void* p;
    cudaGetSymbolAddress(&p, g_xo);   float* xo = (float*)p;
    __half *qkvb, *y1, *at, *y2, *hid;
    cudaGetSymbolAddress(&p, g_qkv); qkvb = (__half*)p;
    cudaGetSymbolAddress(&p, g_y1);  y1   = (__half*)p;
    cudaGetSymbolAddress(&p, g_at);  at   = (__half*)p;
    cudaGetSymbolAddress(&p, g_y2);  y2   = (__half*)p;
    cudaGetSymbolAddress(&p, g_hid); hid  = (__half*)p;
    __half *wq, *wp, *w1, *w2;
    cudaGetSymbolAddress(&p, g_wqkv); wq = (__half*)p;
    cudaGetSymbolAddress(&p, g_wprj); wp = (__half*)p;
    cudaGetSymbolAddress(&p, g_w1);   w1 = (__half*)p;
    cudaGetSymbolAddress(&p, g_w2);   w2 = (__half*)p;

    cudaFuncSetAttribute(attn_kernel, cudaFuncAttributeMaxDynamicSharedMemorySize, ATTN_SMEM);
    cudaFuncSetAttribute(gemm_mma<EPI_NONE, 1>,    cudaFuncAttributeMaxDynamicSharedMemorySize, GT_SMEM);
    cudaFuncSetAttribute(gemm_mma<EPI_GELU, 1>,    cudaFuncAttributeMaxDynamicSharedMemorySize, GT_SMEM);
    cudaFuncSetAttribute(gemm_mma<EPI_RES_MAP, 0>, cudaFuncAttributeMaxDynamicSharedMemorySize, GT_SMEM);
    cudaFuncSetAttribute(gemm_mma<EPI_RES_NAT, 0>, cudaFuncAttributeMaxDynamicSharedMemorySize, GT_SMEM);

    // 0) weight transpose -> fp16 (single launch)
    wconv_all<<<3072, 256>>>(qkv_w, proj_w, ffn_w1, ffn_w2, wq, wp, w1, w2);

    // 1) LN1 with shift+window gather -> fp16
    ln_kernel<<<TOK, 256>>>(x, ln1_g, ln1_b, y1, 1);

    // 2) QKV GEMM -> fp16 qkv
    gemm_mma<EPI_NONE, 1><<<dim3(QKVN / 128, TOK / 128), 128, GT_SMEM>>>(
        y1, wq, qkv_b, nullptr, nullptr, qkvb, TOK, QKVN, CDIM);

    // 3) attention (register-resident P) -> fp16
    attn_kernel<<<NWIN * NHEAD, 128, ATTN_SMEM>>>(qkvb, at);

    // 4) proj GEMM + residual(x) + scatter -> fp32 xo (natural)
    gemm_mma<EPI_RES_MAP, 0><<<dim3(CDIM / 128, TOK / 128), 128, GT_SMEM>>>(
        at, wp, proj_b, x, xo, nullptr, TOK, CDIM, CDIM);

    // 5) LN2 -> fp16
    ln_kernel<<<TOK, 256>>>(xo, ln2_g, ln2_b, y2, 0);

    // 6) FFN1 + GELU -> fp16 hidden
    gemm_mma<EPI_GELU, 1><<<dim3(HIDN / 128, TOK / 128), 128, GT_SMEM>>>(
        y2, w1, ffn_b1, nullptr, nullptr, hid, TOK, HIDN, CDIM);

    // 7) FFN2 + residual(xo) -> out
    gemm_mma<EPI_RES_NAT, 0><<<dim3(CDIM / 128, TOK / 128), 128, GT_SMEM>>>(
        hid, w2, ffn_b2, xo, out, nullptr, TOK, CDIM, HIDN);
}

// round 17
// speedup vs baseline: 1.4862x; 1.4862x over previous
#include <cuda_runtime.h>
#include <cuda_fp16.h>
#include <cstdint>
#include <math.h>

// ---------------- problem constants ----------------
#define TOK   65536          // 2*32*32*32 tokens
#define CDIM  512
#define QKVN  1536
#define HIDN  2048
#define NWIN  1024           // windows total (2 * 8^3)
#define NHEAD 8
#define HD    64

// ---------------- helpers ----------------
__device__ __forceinline__ uint32_t smem_to_u32(const void* p) {
    uint32_t a;
    asm("{ .reg .u64 t; cvta.to.shared.u64 t, %1; cvt.u32.u64 %0, t; }" : "=r"(a) : "l"(p));
    return a;
}

#define CP_ASYNC16(dst, src) \
    asm volatile("cp.async.cg.shared.global [%0], [%1], 16;" :: "r"(dst), "l"(src))
#define CP_COMMIT() asm volatile("cp.async.commit_group;" ::: "memory")
#define CP_WAIT0()  asm volatile("cp.async.wait_group 0;" ::: "memory")
#define CP_WAIT2()  asm volatile("cp.async.wait_group 2;" ::: "memory")

#define LDSM_X4(r0, r1, r2, r3, addr) \
    asm volatile("ldmatrix.sync.aligned.m8n8.x4.shared.b16 {%0,%1,%2,%3}, [%4];" \
                 : "=r"(r0), "=r"(r1), "=r"(r2), "=r"(r3) : "r"(addr))

#define LDSM_X4_T(r0, r1, r2, r3, addr) \
    asm volatile("ldmatrix.sync.aligned.m8n8.x4.trans.shared.b16 {%0,%1,%2,%3}, [%4];" \
                 : "=r"(r0), "=r"(r1), "=r"(r2), "=r"(r3) : "r"(addr))

__device__ __forceinline__ void mma_f16(float* c, const uint32_t* a, const uint32_t* b) {
    asm volatile(
        "mma.sync.aligned.m16n8k16.row.col.f32.f16.f16.f32 "
        "{%0,%1,%2,%3}, {%4,%5,%6,%7}, {%8,%9}, {%0,%1,%2,%3};"
        : "+f"(c[0]), "+f"(c[1]), "+f"(c[2]), "+f"(c[3])
        : "r"(a[0]), "r"(a[1]), "r"(a[2]), "r"(a[3]), "r"(b[0]), "r"(b[1]));
}

// ---------------- scratch (static device memory) ----------------
__device__ float  g_xo  [(size_t)TOK * CDIM];                 // fp32 residual base
__device__ __half g_qkv [(size_t)TOK * QKVN];                 // fp16 qkv
__device__ __half g_y1 [(size_t)TOK * CDIM];
__device__ __half g_at [(size_t)TOK * CDIM];
__device__ __half g_y2 [(size_t)TOK * CDIM];
__device__ __half g_hid[(size_t)TOK * HIDN];
// weight transposed fp16 buffers: [N, K]
__device__ __half g_wqkv[(size_t)QKVN * CDIM];
__device__ __half g_wprj[(size_t)CDIM * CDIM];
__device__ __half g_w1  [(size_t)HIDN * CDIM];
__device__ __half g_w2  [(size_t)CDIM * HIDN];

// window-ordered row r -> natural token index t
__device__ __forceinline__ int wr2t(int r) {
    int n   = r & 63;
    int win = r >> 6;
    int ww  = win & 7, wh = (win >> 3) & 7, wd = (win >> 6) & 7, b = win >> 9;
    int zw  = n & 3,  zh = (n >> 2) & 3,  zd = n >> 4;
    int d = (wd * 4 + zd + 2) & 31;
    int h = (wh * 4 + zh + 2) & 31;
    int w = (ww * 4 + zw + 2) & 31;
    return ((b * 32 + d) * 32 + h) * 32 + w;
}

__device__ __forceinline__ float gelu_exact(float v) {
    return 0.5f * v * (1.0f + erff(v * 0.70710678118654752f));
}

// ---------------- weight transpose -> fp16 (all four weights, one launch) --
__global__ __launch_bounds__(256)
void wconv_all(const float* __restrict__ W0, const float* __restrict__ W1,
               const float* __restrict__ W2, const float* __restrict__ W3,
               __half* __restrict__ T0, __half* __restrict__ T1,
               __half* __restrict__ T2, __half* __restrict__ T3)
{
    __shared__ float tile[32][33];
    int t = blockIdx.x;
    const float* W; __half* Wt; int K, N, u, nx;
    if (t < 768)       { W = W0; Wt = T0; K = 512;  N = 1536; u = t;        nx = 48; }
    else if (t < 1024) { W = W1; Wt = T1; K = 512;  N = 512;  u = t - 768;  nx = 16; }
    else if (t < 2048) { W = W2; Wt = T2; K = 512;  N = 2048; u = t - 1024; nx = 64; }
    else               { W = W3; Wt = T3; K = 2048; N = 512;  u = t - 2048; nx = 16; }
    int n0 = (u % nx) * 32, k0 = (u / nx) * 32;
    int tx = threadIdx.x & 31, ty = threadIdx.x >> 5;   // 32 x 8
    #pragma unroll
    for (int r = 0; r < 4; r++) {
        int kk = ty + r * 8;
        tile[kk][tx] = W[(size_t)(k0 + kk) * N + n0 + tx];
    }
    __syncthreads();
    #pragma unroll
    for (int r = 0; r < 4; r++) {
        int nn = ty + r * 8;
        Wt[(size_t)(n0 + nn) * K + k0 + tx] = __float2half_rn(tile[tx][nn]);
    }
}

// ---------------- LayerNorm -> fp16 (128 thr/row, float4 loads) ------------
__global__ __launch_bounds__(128)
void ln_kernel(const float* __restrict__ X, const float* __restrict__ gam,
               const float* __restrict__ bet, __half* __restrict__ Y, int gather)
{
    __shared__ float red[8];
    int r   = blockIdx.x;
    int src = gather ? wr2t(r) : r;
    int t = threadIdx.x;
    float4 v = *(const float4*)(X + (size_t)src * CDIM + t * 4);
    float s = v.x + v.y + v.z + v.w;
    float q = v.x * v.x + v.y * v.y + v.z * v.z + v.w * v.w;
    #pragma unroll
    for (int off = 16; off > 0; off >>= 1) {
        s += __shfl_xor_sync(0xffffffffu, s, off);
        q += __shfl_xor_sync(0xffffffffu, q, off);
    }
    int w = t >> 5, lane = t & 31;
    if (lane == 0) { red[w] = s; red[4 + w] = q; }
    __syncthreads();
    float s2 = red[0] + red[1] + red[2] + red[3];
    float q2 = red[4] + red[5] + red[6] + red[7];
    float mean = s2 * (1.0f / CDIM);
    float var  = q2 * (1.0f / CDIM) - mean * mean;
    float rstd = rsqrtf(var + 1e-5f);
    float4 gv = *(const float4*)(gam + t * 4);
    float4 bv = *(const float4*)(bet + t * 4);
    float y0 = (v.x - mean) * rstd * gv.x + bv.x;
    float y1 = (v.y - mean) * rstd * gv.y + bv.y;
    float y2 = (v.z - mean) * rstd * gv.z + bv.z;
    float y3 = (v.w - mean) * rstd * gv.w + bv.w;
    __half2 h0 = __halves2half2(__float2half_rn(y0), __float2half_rn(y1));
    __half2 h1 = __halves2half2(__float2half_rn(y2), __float2half_rn(y3));
    uint2 pk = make_uint2(*(uint32_t*)&h0, *(uint32_t*)&h1);
    *(uint2*)(Y + (size_t)r * CDIM + t * 4) = pk;
}

// ---------------- tensor-core GEMM via mma.sync (pure fp16, fp32 acc) ------
// CTA 128x128, FOUR warps in 2(M)x2(N), warp tile 64x64, BK=32, 4-stage pipeline.
// (R14 configuration: best-known GEMM state.)
#define EPI_NONE    0
#define EPI_GELU    1
#define EPI_RES_MAP 2
#define EPI_RES_NAT 3

#define ROWPITCH 80
#define REG_A    0
#define REG_B    10240
#define BUFSZ    20480
#define NSTAGE   4
#define GT_SMEM  (NSTAGE * BUFSZ)

template<int EPI, int OUTH>
__global__ __launch_bounds__(128, 2)
void gemm_mma(const __half* __restrict__ A, const __half* __restrict__ B,
              const float* __restrict__ bias, const float* __restrict__ R,
              float* __restrict__ C, __half* __restrict__ Ch, int M, int N, int K)
{
    extern __shared__ char sm[];
    const uint32_t smb = smem_to_u32(sm);
    const int tid  = threadIdx.x;
    const int wid  = tid >> 5, lane = tid & 31;
    const int wm   = wid & 1,  wn   = wid >> 1;          // 2(M) x 2(N)
    const int row0 = blockIdx.y * 128, col0 = blockIdx.x * 128;

    const int g = lane >> 3, r = lane & 7;
    const uint32_t aoff = (uint32_t)((wm * 64 + (g & 1) * 8 + r) * ROWPITCH + (g >> 1) * 16);
    const uint32_t boff = (uint32_t)((wn * 64 + (g >> 1) * 8 + r) * ROWPITCH + (g & 1) * 16);

    float acc[4][8][4];
    #pragma unroll
    for (int i = 0; i < 4; i++)
        #pragma unroll
        for (int j = 0; j < 8; j++)
            #pragma unroll
            for (int e = 0; e < 4; e++) acc[i][j][e] = 0.f;

    const int NC = K >> 5;

    // loader: A 128 rows x 4 segs + B 128 rows x 4 segs = 1024 segs / 128 thr = 8 each
    auto load_chunk = [&](int kc, int buf) {
        const uint32_t bb = smb + buf * BUFSZ;
        #pragma unroll
        for (int i = 0; i < 4; i++) {
            int u   = tid + (i << 7);          // 0..511
            int row = u >> 2, seg = u & 3;
            uint32_t off = (uint32_t)(row * ROWPITCH + seg * 16);
            CP_ASYNC16(bb + REG_A + off, A + (size_t)(row0 + row) * K + kc + seg * 8);
            CP_ASYNC16(bb + REG_B + off, B + (size_t)(col0 + row) * K + kc + seg * 8);
        }
        CP_COMMIT();
    };

    // prologue: stages 0..2 in flight
    load_chunk(0, 0);
    load_chunk(32, 1);
    load_chunk(64, 2);

    for (int c = 0; c < NC; c++) {
        CP_WAIT2();
        __syncthreads();
        const uint32_t ab = smb + (c & 3) * BUFSZ;

        if (c + 3 < NC) load_chunk((c + 3) * 32, (c + 3) & 3);

        #pragma unroll
        for (int s = 0; s < 2; s++) {
            uint32_t ah[4][4], bh[8][2];
            #pragma unroll
            for (int mi = 0; mi < 4; mi++) {
                uint32_t addr = ab + aoff + mi * (16 * ROWPITCH) + s * 32;
                LDSM_X4(ah[mi][0], ah[mi][1], ah[mi][2], ah[mi][3], addr + REG_A);
            }
            #pragma unroll
            for (int nj = 0; nj < 4; nj++) {
                uint32_t addr = ab + boff + nj * (16 * ROWPITCH) + s * 32;
                LDSM_X4(bh[nj*2][0], bh[nj*2][1], bh[nj*2+1][0], bh[nj*2+1][1], addr + REG_B);
            }
            #pragma unroll
            for (int mi = 0; mi < 4; mi++)
                #pragma unroll
                for (int ni = 0; ni < 8; ni++)
                    mma_f16(acc[mi][ni], ah[mi], bh[ni]);
        }
    }

    // ---- epilogue ----
    const int qrow = lane >> 2;
    const int qcol = (lane & 3) * 2;
    #pragma unroll
    for (int mi = 0; mi < 4; mi++) {
        int gr0 = row0 + wm * 64 + mi * 16 + qrow;
        int gr1 = gr0 + 8;
        int or0 = (EPI == EPI_RES_MAP) ? wr2t(gr0) : gr0;
        int or1 = (EPI == EPI_RES_MAP) ? wr2t(gr1) : gr1;
        #pragma unroll
        for (int ni = 0; ni < 8; ni++) {
            int col = col0 + wn * 64 + ni * 8 + qcol;
            float b0 = bias[col], b1 = bias[col + 1];
            float v00 = acc[mi][ni][0] + b0, v01 = acc[mi][ni][1] + b1;
            float v10 = acc[mi][ni][2] + b0, v11 = acc[mi][ni][3] + b1;
            if (EPI == EPI_GELU) {
                v00 = gelu_exact(v00); v01 = gelu_exact(v01);
                v10 = gelu_exact(v10); v11 = gelu_exact(v11);
            }
            if (EPI == EPI_RES_MAP || EPI == EPI_RES_NAT) {
                float2 r0v = *(const float2*)(R + (size_t)or0 * N + col);
                float2 r1v = *(const float2*)(R + (size_t)or1 * N + col);
                v00 += r0v.x; v01 += r0v.y; v10 += r1v.x; v11 += r1v.y;
            }
            if (OUTH) {
                *(__half2*)(Ch + (size_t)or0 * N + col) =
                    __halves2half2(__float2half_rn(v00), __float2half_rn(v01));
                *(__half2*)(Ch + (size_t)or1 * N + col) =
                    __halves2half2(__float2half_rn(v10), __float2half_rn(v11));
            } else {
                *(float2*)(C + (size_t)or0 * N + col) = make_float2(v00, v01);
                *(float2*)(C + (size_t)or1 * N + col) = make_float2(v10, v11);
            }
        }
    }
}

// ---------------- tensor-core windowed attention, register-resident P ------
#define AP 72        // half pitch (144 B)
#define ATTN_SMEM (3 * 64 * AP * 2)   // q,k,v only: 27648 B

__global__ __launch_bounds__(128)
void attn_kernel(const __half* __restrict__ qkv, __half* __restrict__ out)
{
    extern __shared__ char smc[];
    __half* qs = (__half*)smc;                  // 64 x 72
    __half* ks = qs + 64 * AP;
    __half* vs = ks + 64 * AP;
    const uint32_t qb = smem_to_u32(qs), kb = smem_to_u32(ks), vb = smem_to_u32(vs);

    const int tid = threadIdx.x, w = tid >> 5, lane = tid & 31;
    const int win = blockIdx.x >> 3, head = blockIdx.x & 7;
    const __half* src = qkv + (size_t)win * 64 * QKVN + head * HD;

    #pragma unroll
    for (int j = 0; j < 12; j++) {
        int u = tid + (j << 7);
        int tile = u >> 9, rem = u & 511;
        int row = rem >> 3, seg = rem & 7;
        uint32_t db = (tile == 0 ? qb : (tile == 1 ? kb : vb)) + row * 144 + seg * 16;
        CP_ASYNC16(db, src + tile * 512 + (size_t)row * QKVN + seg * 8);
    }
    CP_COMMIT();
    CP_WAIT0();
    __syncthreads();

    const int g = lane >> 3, r = lane & 7;
    const uint32_t a_q = qb + (w * 16 + (g & 1) * 8 + r) * 144 + (g >> 1) * 16;

    // ---- S = Q K^T ----
    float sacc[8][4];
    #pragma unroll
    for (int i = 0; i < 8; i++)
        #pragma unroll
        for (int e = 0; e < 4; e++) sacc[i][e] = 0.f;
    #pragma unroll
    for (int s = 0; s < 4; s++) {
        uint32_t af[4];
        LDSM_X4(af[0], af[1], af[2], af[3], a_q + s * 32);
        #pragma unroll
        for (int ng = 0; ng < 4; ng++) {
            uint32_t bf[4];
            LDSM_X4(bf[0], bf[1], bf[2], bf[3],
                    kb + ((g >> 1) * 8 + r + ng * 16) * 144 + (g & 1) * 16 + s * 32);
            mma_f16(sacc[ng * 2],     af, &bf[0]);
            mma_f16(sacc[ng * 2 + 1], af, &bf[2]);
        }
    }

    // ---- softmax (quad reduce) ----
    float mx0 = -1e30f, mx1 = -1e30f;
    #pragma unroll
    for (int i = 0; i < 8; i++) {
        sacc[i][0] *= 0.125f; sacc[i][1] *= 0.125f;
        sacc[i][2] *= 0.125f; sacc[i][3] *= 0.125f;
        mx0 = fmaxf(mx0, fmaxf(sacc[i][0], sacc[i][1]));
        mx1 = fmaxf(mx1, fmaxf(sacc[i][2], sacc[i][3]));
    }
    mx0 = fmaxf(mx0, __shfl_xor_sync(0xffffffffu, mx0, 1));
    mx0 = fmaxf(mx0, __shfl_xor_sync(0xffffffffu, mx0, 2));
    mx1 = fmaxf(mx1, __shfl_xor_sync(0xffffffffu, mx1, 1));
    mx1 = fmaxf(mx1, __shfl_xor_sync(0xffffffffu, mx1, 2));
    float sm0 = 0.f, sm1 = 0.f;
    #pragma unroll
    for (int i = 0; i < 8; i++) {
        sacc[i][0] = __expf(sacc[i][0] - mx0);
        sacc[i][1] = __expf(sacc[i][1] - mx0);
        sacc[i][2] = __expf(sacc[i][2] - mx1);
        sacc[i][3] = __expf(sacc[i][3] - mx1);
        sm0 += sacc[i][0] + sacc[i][1];
        sm1 += sacc[i][2] + sacc[i][3];
    }
    sm0 += __shfl_xor_sync(0xffffffffu, sm0, 1);
    sm0 += __shfl_xor_sync(0xffffffffu, sm0, 2);
    sm1 += __shfl_xor_sync(0xffffffffu, sm1, 1);
    sm1 += __shfl_xor_sync(0xffffffffu, sm1, 2);
    const float inv0 = 1.0f / sm0, inv1 = 1.0f / sm1;

    // ---- pack P into A-fragments ----
    uint32_t pa[4][4];
    #pragma unroll
    for (int t = 0; t < 4; t++) {
        __half2 h;
        h = __halves2half2(__float2half_rn(sacc[2*t][0] * inv0),
                           __float2half_rn(sacc[2*t][1] * inv0));
        pa[t][0] = *(uint32_t*)&h;
        h = __halves2half2(__float2half_rn(sacc[2*t][2] * inv1),
                           __float2half_rn(sacc[2*t][3] * inv1));
        pa[t][1] = *(uint32_t*)&h;
        h = __halves2half2(__float2half_rn(sacc[2*t+1][0] * inv0),
                           __float2half_rn(sacc[2*t+1][1] * inv0));
        pa[t][2] = *(uint32_t*)&h;
        h = __halves2half2(__float2half_rn(sacc[2*t+1][2] * inv1),
                           __float2half_rn(sacc[2*t+1][3] * inv1));
        pa[t][3] = *(uint32_t*)&h;
    }

    // ---- O = P V ----
    float oacc[8][4];
    #pragma unroll
    for (int i = 0; i < 8; i++)
        #pragma unroll
        for (int e = 0; e < 4; e++) oacc[i][e] = 0.f;
    #pragma unroll
    for (int kk = 0; kk < 2; kk++) {
        #pragma unroll
        for (int nd = 0; nd < 8; nd++) {
            uint32_t vf[4];
            LDSM_X4_T(vf[0], vf[1], vf[2], vf[3],
                      vb + (kk * 32 + g * 8 + r) * 144 + nd * 16);
            mma_f16(oacc[nd], pa[2*kk],     &vf[0]);
            mma_f16(oacc[nd], pa[2*kk + 1], &vf[2]);
        }
    }

    // ---- store O ----
    const int qr = lane >> 2, qc = (lane & 3) * 2;
    __half* dst = out + ((size_t)win * 64) * CDIM + head * HD;
    const int m0 = w * 16 + qr;
    #pragma unroll
    for (int nd = 0; nd < 8; nd++) {
        int d = nd * 8 + qc;
        *(__half2*)(dst + (size_t)m0 * CDIM + d) =
            __halves2half2(__float2half_rn(oacc[nd][0]), __float2half_rn(oacc[nd][1]));
        *(__half2*)(dst + (size_t)(m0 + 8) * CDIM + d) =
            __halves2half2(__float2half_rn(oacc[nd][2]), __float2half_rn(oacc[nd][3]));
    }
}

// ---------------- launch ----------------
extern "C" void kernel_launch(void* const* d_in, const int* in_sizes, int n_in,
                              void* d_out, int out_size)
{
    const float* x      = (const float*)d_in[0];
    const float* ln1_g  = (const float*)d_in[1];
    const float* ln1_b  = (const float*)d_in[2];
    const float* qkv_w  = (const float*)d_in[3];
    const float* qkv_b  = (const float*)d_in[4];
    const float* proj_w = (const float*)d_in[5];
    const float* proj_b = (const float*)d_in[6];
    const float* ln2_g  = (const float*)d_in[7];
    const float* ln2_b  = (const float*)d_in[8];
    const float* ffn_w1 = (const float*)d_in[9];
    const float* ffn_b1 = (const float*)d_in[10];
    const float* ffn_w2 = (const float*)d_in[11];
    const float* ffn_b2 = (const float*)d_in[12];
    float* out = (float*)d_out;

    void* p;
    cudaGetSymbolAddress(&p, g_xo);   float* xo = (float*)p;
    __half *qkvb, *y1, *at, *y2, *hid;
    cudaGetSymbolAddress(&p, g_qkv); qkvb = (__half*)p;
    cudaGetSymbolAddress(&p, g_y1);  y1   = (__half*)p;
    cudaGetSymbolAddress(&p, g_at);  at   = (__half*)p;
    cudaGetSymbolAddress(&p, g_y2);  y2   = (__half*)p;
    cudaGetSymbolAddress(&p, g_hid); hid  = (__half*)p;
    __half *wq, *wp, *w1, *w2;
    cudaGetSymbolAddress(&p, g_wqkv); wq = (__half*)p;
    cudaGetSymbolAddress(&p, g_wprj); wp = (__half*)p;
    cudaGetSymbolAddress(&p, g_w1);   w1 = (__half*)p;
    cudaGetSymbolAddress(&p, g_w2);   w2 = (__half*)p;

    cudaFuncSetAttribute(attn_kernel, cudaFuncAttributeMaxDynamicSharedMemorySize, ATTN_SMEM);
    cudaFuncSetAttribute(gemm_mma<EPI_NONE, 1>,    cudaFuncAttributeMaxDynamicSharedMemorySize, GT_SMEM);
    cudaFuncSetAttribute(gemm_mma<EPI_GELU, 1>,    cudaFuncAttributeMaxDynamicSharedMemorySize, GT_SMEM);
    cudaFuncSetAttribute(gemm_mma<EPI_RES_MAP, 0>, cudaFuncAttributeMaxDynamicSharedMemorySize, GT_SMEM);
    cudaFuncSetAttribute(gemm_mma<EPI_RES_NAT, 0>, cudaFuncAttributeMaxDynamicSharedMemorySize, GT_SMEM);

    // 0) weight transpose -> fp16 (single launch)
    wconv_all<<<3072, 256>>>(qkv_w, proj_w, ffn_w1, ffn_w2, wq, wp, w1, w2);

    // 1) LN1 with shift+window gather -> fp16
    ln_kernel<<<TOK, 128>>>(x, ln1_g, ln1_b, y1, 1);

    // 2) QKV GEMM -> fp16 qkv
    gemm_mma<EPI_NONE, 1><<<dim3(QKVN / 128, TOK / 128), 128, GT_SMEM>>>(
        y1, wq, qkv_b, nullptr, nullptr, qkvb, TOK, QKVN, CDIM);

    // 3) attention (register-resident P) -> fp16
    attn_kernel<<<NWIN * NHEAD, 128, ATTN_SMEM>>>(qkvb, at);

    // 4) proj GEMM + residual(x) + scatter -> fp32 xo (natural)
    gemm_mma<EPI_RES_MAP, 0><<<dim3(CDIM / 128, TOK / 128), 128, GT_SMEM>>>(
        at, wp, proj_b, x, xo, nullptr, TOK, CDIM, CDIM);

    // 5) LN2 -> fp16
    ln_kernel<<<TOK, 128>>>(xo, ln2_g, ln2_b, y2, 0);

    // 6) FFN1 + GELU -> fp16 hidden
    gemm_mma<EPI_GELU, 1><<<dim3(HIDN / 128, TOK / 128), 128, GT_SMEM>>>(
        y2, w1, ffn_b1, nullptr, nullptr, hid, TOK, HIDN, CDIM);

    // 7) FFN2 + residual(xo) -> out
    gemm_mma<EPI_RES_NAT, 0><<<dim3(CDIM / 128, TOK / 128), 128, GT_SMEM>>>(
        hid, w2, ffn_b2, xo, out, nullptr, TOK, CDIM, HIDN);
}